// round 11
// baseline (speedup 1.0000x reference)
#include <cuda_runtime.h>
#include <cuda_fp16.h>

#define Dd 48
#define Hh 256
#define Ww 256
#define DMk 48
#define HMk 128
#define WMk 128
#define PHn 4
#define CS (Dd * Hh * Ww * 2)          // 6,291,456 floats per phase slab
#define NPIX (Dd * Hh * Ww)            // 3,145,728 pixels
#define MVF_CH (DMk * HMk * WMk)       // 786,432 floats per mvf channel

// 25 MB fp16 x-pair scratch: g_pair[i][0] = half2(img[i].c0,   img[i].c1)
//                            g_pair[i][1] = half2(img[i+1].c0, img[i+1].c1)
// (x+1 clamped within the row). One aligned 8B load = both channels, both x-taps.
__device__ __align__(8) __half2 g_pair[NPIX][2];

// ---------------------------------------------------------------------------
// Prep: build fp16 pair scratch AND write passthrough slab out[:,0] = image.
// ---------------------------------------------------------------------------
__global__ void __launch_bounds__(256)
prep_kernel(const float2* __restrict__ img2, float2* __restrict__ out2) {
    int i = blockIdx.x * blockDim.x + threadIdx.x;
    if (i >= NPIX) return;
    int x = i & (Ww - 1);
    float2 a = __ldg(img2 + i);
    float2 b = __ldg(img2 + i + (x < Ww - 1 ? 1 : 0));
    g_pair[i][0] = __floats2half2_rn(a.x, a.y);
    g_pair[i][1] = __floats2half2_rn(b.x, b.y);
    out2[i] = a;
}

__device__ __forceinline__ __half2 h2_of(unsigned u) {
    __half2 h;
    *reinterpret_cast<unsigned*>(&h) = u;
    return h;
}
__device__ __forceinline__ __half2 h2lerp(__half2 a, __half2 b, __half2 w) {
    return __hfma2(w, __hsub2(b, a), a);   // a + w*(b-a)
}

__device__ __forceinline__ bool is_interior(float cz, float cy, float cx) {
    return (cz >= 0.f) & (cz < (float)(Dd - 1)) &
           (cy >= 0.f) & (cy < (float)(Hh - 1)) &
           (cx >= 0.f) & (cx < (float)(Ww - 1));
}

__device__ __forceinline__ void fast_addrs(float cz, float cy, float cx,
                                           const uint2*& q,
                                           __half2& wz, __half2& wy, __half2& wx) {
    int z0 = (int)cz, y0 = (int)cy, x0 = (int)cx;   // nonneg: trunc==floor
    wz = __float2half2_rn(cz - (float)z0);
    wy = __float2half2_rn(cy - (float)y0);
    wx = __float2half2_rn(cx - (float)x0);
    q  = reinterpret_cast<const uint2*>(g_pair) + ((z0 * Hh + y0) * Ww + x0);
}

__device__ __forceinline__ float2 fast_lerp(uint2 r00, uint2 r01,
                                            uint2 r10, uint2 r11,
                                            __half2 wz, __half2 wy, __half2 wx) {
    __half2 x00 = h2lerp(h2_of(r00.x), h2_of(r00.y), wx);
    __half2 x01 = h2lerp(h2_of(r01.x), h2_of(r01.y), wx);
    __half2 x10 = h2lerp(h2_of(r10.x), h2_of(r10.y), wx);
    __half2 x11 = h2lerp(h2_of(r11.x), h2_of(r11.y), wx);
    __half2 y0v = h2lerp(x00, x01, wy);
    __half2 y1v = h2lerp(x10, x11, wy);
    return __half22float2(h2lerp(y0v, y1v, wz));
}

// ---------------------------------------------------------------------------
// Single-sample path with warp-uniform fast/slow split (boundary warps).
// ---------------------------------------------------------------------------
__device__ __forceinline__ float2 sample3d_h(float cz, float cy, float cx) {
    bool interior = is_interior(cz, cy, cx);
    if (__all_sync(0xffffffffu, interior)) {
        const uint2* q; __half2 wz, wy, wx;
        fast_addrs(cz, cy, cx, q, wz, wy, wx);
        uint2 r00 = __ldg(q);
        uint2 r01 = __ldg(q + Ww);
        uint2 r10 = __ldg(q + Hh * Ww);
        uint2 r11 = __ldg(q + Hh * Ww + Ww);
        return fast_lerp(r00, r01, r10, r11, wz, wy, wx);
    }

    // --- boundary path: exact fp32 weights, per-axis validity, clamped idx ---
    float zf = floorf(cz), yf = floorf(cy), xf = floorf(cx);
    float fz = cz - zf, fy = cy - yf, fx = cx - xf;
    int z0 = (int)zf, y0 = (int)yf, x0 = (int)xf;
    int z1 = z0 + 1, y1 = y0 + 1;

    float wzv[2], wyv[2];
    wzv[0] = (1.f - fz) * (((unsigned)z0 < (unsigned)Dd) ? 1.f : 0.f);
    wzv[1] = fz         * (((unsigned)z1 < (unsigned)Dd) ? 1.f : 0.f);
    wyv[0] = (1.f - fy) * (((unsigned)y0 < (unsigned)Hh) ? 1.f : 0.f);
    wyv[1] = fy         * (((unsigned)y1 < (unsigned)Hh) ? 1.f : 0.f);
    float wx0 = (1.f - fx) * (((unsigned)x0       < (unsigned)Ww) ? 1.f : 0.f);
    float wx1 = fx         * (((unsigned)(x0 + 1) < (unsigned)Ww) ? 1.f : 0.f);

    int zi[2] = {min(max(z0, 0), Dd - 1), min(max(z1, 0), Dd - 1)};
    int yi[2] = {min(max(y0, 0), Hh - 1), min(max(y1, 0), Hh - 1)};
    int xc0   = min(max(x0, 0), Ww - 1);
    bool hiOK = (x0 >= 0);   // x0 == -1: both x-taps resolve to img[0]

    float ax = 0.f, ay = 0.f;
#pragma unroll
    for (int a = 0; a < 2; a++) {
#pragma unroll
        for (int b = 0; b < 2; b++) {
            float wzy = wzv[a] * wyv[b];
            uint2 raw = __ldg(reinterpret_cast<const uint2*>(
                                  g_pair[(zi[a] * Hh + yi[b]) * Ww + xc0]));
            float2 lo = __half22float2(h2_of(raw.x));
            float2 hi = __half22float2(h2_of(raw.y));
            float c1x = hiOK ? hi.x : lo.x;
            float c1y = hiOK ? hi.y : lo.y;
            ax = fmaf(wzy, fmaf(wx0, lo.x, wx1 * c1x), ax);
            ay = fmaf(wzy, fmaf(wx0, lo.y, wx1 * c1y), ay);
        }
    }
    return make_float2(ax, ay);
}

// ---------------------------------------------------------------------------
// Fused warp kernel, 4 samples per thread (y-pair x x-split):
// block = 128 threads; grid = (Hh/2, Dd, PHn). Thread t handles output
// pixels {x = t, t+128} x {y = 2gy, 2gy+1}. All 16 corner loads issue before
// any lerp (MLP=16). Lane x-stride stays 1 (8B) so sector count per
// warp-load is unchanged. mvf rows gy-1, gy, gy+1 serve both output rows.
// ---------------------------------------------------------------------------
__global__ void __launch_bounds__(128)
warp_kernel(const float* __restrict__ mvf, float* __restrict__ out) {
    __shared__ float ymixE[3][WMk];   // for output row y = 2*gy   (even)
    __shared__ float ymixO[3][WMk];   // for output row y = 2*gy+1 (odd)

    int tx = threadIdx.x;      // 0..127
    int gy = blockIdx.x;       // 0..127 -> rows 2gy, 2gy+1
    int z  = blockIdx.y;       // 0..47
    int ph = blockIdx.z;       // 0..3

    int gym1 = (gy > 0) ? gy - 1 : 0;
    int gyp1 = (gy < HMk - 1) ? gy + 1 : HMk - 1;

    const float* mbase = mvf + (size_t)ph * 3 * MVF_CH + (size_t)z * HMk * WMk;
#pragma unroll
    for (int c = 0; c < 3; c++) {
        const float* ch = mbase + (size_t)c * MVF_CH;
        float a = __ldg(ch + gym1 * WMk + tx);
        float m = __ldg(ch + gy   * WMk + tx);
        float b = __ldg(ch + gyp1 * WMk + tx);
        ymixE[c][tx] = fmaf(0.25f, a, 0.75f * m);   // even: .25*prev + .75*cur
        ymixO[c][tx] = fmaf(0.75f, m, 0.25f * b);   // odd:  .75*cur + .25*next
    }
    __syncthreads();

    int ye = 2 * gy, yo = 2 * gy + 1;
    float2* o2 = (float2*)(out + (size_t)(1 + ph) * CS);

    // Two x-positions per thread: xs = tx and tx + 128.
#pragma unroll
    for (int half = 0; half < 2; half++) {
        int xs = tx + half * 128;

        int  k    = xs >> 1;
        bool xodd = (xs & 1) != 0;
        int  xa   = xodd ? k : (k > 0 ? k - 1 : 0);
        int  xb   = xodd ? (k < WMk - 1 ? k + 1 : WMk - 1) : k;
        float wxa = xodd ? 0.75f : 0.25f;
        float wxb = 1.f - wxa;

        float ve[3], vo[3];
#pragma unroll
        for (int c = 0; c < 3; c++) {
            ve[c] = fmaf(wxa, ymixE[c][xa], wxb * ymixE[c][xb]);
            vo[c] = fmaf(wxa, ymixO[c][xa], wxb * ymixO[c][xb]);
        }

        // flow scale (1, 2, 2); coords are absolute voxel coordinates
        float cze = (float)z + ve[0], cye = (float)ye + 2.f * ve[1],
              cxe = (float)xs + 2.f * ve[2];
        float czo = (float)z + vo[0], cyo = (float)yo + 2.f * vo[1],
              cxo = (float)xs + 2.f * vo[2];

        float2 re, ro;
        bool both = is_interior(cze, cye, cxe) & is_interior(czo, cyo, cxo);
        if (__all_sync(0xffffffffu, both)) {
            const uint2 *qe, *qo; __half2 wze, wye, wxe, wzo, wyo, wxo;
            fast_addrs(cze, cye, cxe, qe, wze, wye, wxe);
            fast_addrs(czo, cyo, cxo, qo, wzo, wyo, wxo);
            uint2 e00 = __ldg(qe);
            uint2 e01 = __ldg(qe + Ww);
            uint2 e10 = __ldg(qe + Hh * Ww);
            uint2 e11 = __ldg(qe + Hh * Ww + Ww);
            uint2 o00 = __ldg(qo);
            uint2 o01 = __ldg(qo + Ww);
            uint2 o10 = __ldg(qo + Hh * Ww);
            uint2 o11 = __ldg(qo + Hh * Ww + Ww);
            re = fast_lerp(e00, e01, e10, e11, wze, wye, wxe);
            ro = fast_lerp(o00, o01, o10, o11, wzo, wyo, wxo);
        } else {
            re = sample3d_h(cze, cye, cxe);
            ro = sample3d_h(czo, cyo, cxo);
        }

        o2[(z * Hh + ye) * Ww + xs] = re;
        o2[(z * Hh + yo) * Ww + xs] = ro;
    }
}

// ---------------------------------------------------------------------------
extern "C" void kernel_launch(void* const* d_in, const int* in_sizes, int n_in,
                              void* d_out, int out_size) {
    const float* image = (const float*)d_in[0];   // (1,1,48,256,256,2) f32
    const float* mvf   = (const float*)d_in[1];   // (1,4,3,48,128,128) f32
    float* out = (float*)d_out;                   // (1,5,48,256,256,2) f32

    prep_kernel<<<(NPIX + 255) / 256, 256>>>((const float2*)image,
                                             (float2*)out);

    dim3 grid(Hh / 2, Dd, PHn);
    warp_kernel<<<grid, 128>>>(mvf, out);
}